// round 11
// baseline (speedup 1.0000x reference)
#include <cuda_runtime.h>
#include <cuda_fp16.h>
#include <cstdint>

// Problem constants
#define NPIX    100352      // 32*56*56 output pixels
#define CCH     256         // channels (in == out)
#define NW_ELEM 589824      // 3*3*256*256 weights
#define KTOT    2304        // 9 taps * 256 in-ch
#define XELEMS  25690112    // 32*56*56*256

// ---------------- scratch (device globals; no allocation) ----------------
__device__ __half g_xf[XELEMS];             // fp16 x
__device__ __half g_Wq[CCH * KTOT];         // ternary W, [oc][tap*256+ic], fp16
__device__ float g_part1[256];
__device__ float g_part2[256];
__device__ int   g_pcnt[256];
__device__ float g_t;
__device__ float g_alpha;

// ---------------- helpers ----------------
static __device__ __forceinline__ uint32_t smem_u32(const void* p) {
    uint32_t a;
    asm("{ .reg .u64 t; cvta.to.shared.u64 t, %1; cvt.u32.u64 %0, t; }"
        : "=r"(a) : "l"(p));
    return a;
}

static __device__ __forceinline__ void cp_async16(uint32_t dst, const void* src, uint32_t src_sz) {
    asm volatile("cp.async.cg.shared.global [%0], [%1], 16, %2;"
                 :: "r"(dst), "l"(src), "r"(src_sz));
}
#define CP_COMMIT() asm volatile("cp.async.commit_group;" ::: "memory")
#define CP_WAIT(n)  asm volatile("cp.async.wait_group %0;" :: "n"(n) : "memory")

static __device__ __forceinline__ void ldm_x4(uint32_t* r, uint32_t addr) {
    asm volatile("ldmatrix.sync.aligned.m8n8.x4.shared.b16 {%0,%1,%2,%3}, [%4];"
                 : "=r"(r[0]), "=r"(r[1]), "=r"(r[2]), "=r"(r[3]) : "r"(addr));
}

static __device__ __forceinline__ void mma_fp16(float* c, const uint32_t* a, const uint32_t* b) {
    asm volatile(
        "mma.sync.aligned.m16n8k16.row.col.f32.f16.f16.f32 "
        "{%0,%1,%2,%3}, {%4,%5,%6,%7}, {%8,%9}, {%0,%1,%2,%3};"
        : "+f"(c[0]), "+f"(c[1]), "+f"(c[2]), "+f"(c[3])
        : "r"(a[0]), "r"(a[1]), "r"(a[2]), "r"(a[3]), "r"(b[0]), "r"(b[1]));
}

// ---------------- preprocessing kernels ----------------

// Fused: x -> fp16 conversion (all blocks) + |W| block-partials (blocks 0..255)
__global__ void k_cvt_redabs(const float* __restrict__ x, const float* __restrict__ W) {
    // fp16 conversion slice
    int i = (blockIdx.x * 256 + threadIdx.x) * 4;
    float4 v = *reinterpret_cast<const float4*>(x + i);
    __half2 a = __floats2half2_rn(v.x, v.y);
    __half2 b = __floats2half2_rn(v.z, v.w);
    uint2 pv;
    pv.x = *reinterpret_cast<uint32_t*>(&a);
    pv.y = *reinterpret_cast<uint32_t*>(&b);
    *reinterpret_cast<uint2*>(&g_xf[i]) = pv;

    // |W| reduction on the first 256 blocks
    if (blockIdx.x < 256) {
        __shared__ float s[256];
        float acc = 0.f;
        for (int j = blockIdx.x * 256 + threadIdx.x; j < NW_ELEM; j += 256 * 256)
            acc += fabsf(W[j]);
        s[threadIdx.x] = acc;
        __syncthreads();
        for (int o = 128; o > 0; o >>= 1) {
            if (threadIdx.x < o) s[threadIdx.x] += s[threadIdx.x + o];
            __syncthreads();
        }
        if (threadIdx.x == 0) g_part1[blockIdx.x] = s[0];
    }
}

__global__ void k_fin_t() {
    __shared__ float s[256];
    s[threadIdx.x] = g_part1[threadIdx.x];
    __syncthreads();
    for (int o = 128; o > 0; o >>= 1) {
        if (threadIdx.x < o) s[threadIdx.x] += s[threadIdx.x + o];
        __syncthreads();
    }
    if (threadIdx.x == 0) g_t = 0.7f * s[0] / (float)NW_ELEM;
}

__global__ void k_red_alpha(const float* __restrict__ W) {
    __shared__ float s[256];
    __shared__ int   sc[256];
    float t = g_t;
    float acc = 0.f;
    int cnt = 0;
    for (int i = blockIdx.x * 256 + threadIdx.x; i < NW_ELEM; i += 256 * 256) {
        float w = W[i];
        if (w > t)       { acc += w;  cnt++; }
        else if (w < -t) { acc -= w;  cnt++; }
    }
    s[threadIdx.x] = acc; sc[threadIdx.x] = cnt;
    __syncthreads();
    for (int o = 128; o > 0; o >>= 1) {
        if (threadIdx.x < o) { s[threadIdx.x] += s[threadIdx.x + o]; sc[threadIdx.x] += sc[threadIdx.x + o]; }
        __syncthreads();
    }
    if (threadIdx.x == 0) { g_part2[blockIdx.x] = s[0]; g_pcnt[blockIdx.x] = sc[0]; }
}

__global__ void k_fin_alpha() {
    __shared__ float s[256];
    __shared__ int   sc[256];
    s[threadIdx.x] = g_part2[threadIdx.x];
    sc[threadIdx.x] = g_pcnt[threadIdx.x];
    __syncthreads();
    for (int o = 128; o > 0; o >>= 1) {
        if (threadIdx.x < o) { s[threadIdx.x] += s[threadIdx.x + o]; sc[threadIdx.x] += sc[threadIdx.x + o]; }
        __syncthreads();
    }
    if (threadIdx.x == 0) g_alpha = s[0] / (float)sc[0];
}

// ternarize W into fp16 GEMM-B layout: g_Wq[oc][tap*256+ic]
__global__ void k_quant(const float* __restrict__ W) {
    int i = blockIdx.x * 256 + threadIdx.x;       // i = (tap*256+ic)*256 + oc
    if (i >= NW_ELEM) return;
    float t = g_t;
    float w = W[i];
    float q = (w > t) ? 1.f : ((w < -t) ? -1.f : 0.f);
    int oc = i & 255;
    int rest = i >> 8;                            // tap*256 + ic
    g_Wq[oc * KTOT + rest] = __float2half_rn(q);
}

// ---------------- main implicit-GEMM conv (mma.sync, arch-generic) -----------
// CTA: 256 threads (8 warps), tile M=64 (pixels) x N=128 (out-ch half).
// Grid: (1568 M-tiles, 2 N-tiles) = 3136 CTAs; 2 CTAs/SM (72KB smem each).
// K loop: 36 steps of (tap 0..8, chan-block 0..3), K=64/step; stages
//   A[64x64], B[128x64] (fp16, 128B rows, XOR swizzle) in a 3-stage
//   cp.async pipeline (24KB/stage). Order per step (R8-proven):
//   CP_WAIT(1) -> __syncthreads -> issue load(s+2) -> compute(s).
// Warp grid 2(M) x 4(N); warp tile 32x32 -> 2x4 m16n8k16 mma, 32 accum regs.

#define STAGE_BYTES 24576
#define A_OFF 0
#define B_OFF 8192
#define NSTEPS 36

__global__ void __launch_bounds__(256, 2)
k_conv(const float* __restrict__ bias, float* __restrict__ out) {
    extern __shared__ __align__(1024) uint8_t smem[];
    const uint32_t sbase = smem_u32(smem);

    const int tid = threadIdx.x;
    const int wid = tid >> 5;
    const int lid = tid & 31;
    const int wy  = wid & 1;        // M half (0/1 -> 32 rows)
    const int wx  = wid >> 1;       // N col (0..3 -> 32 out-ch)
    const int mtile = blockIdx.x;
    const int ntile = blockIdx.y;

    // ---- loader precompute ----
    const int seg = tid & 7;        // 16B segment within 128B row
    const int r0  = tid >> 3;       // base row 0..31
    // A rows: r0 + {0,32}
    int nimg[2], hh[2], ww[2];
    #pragma unroll
    for (int i = 0; i < 2; i++) {
        int p = mtile * 64 + r0 + i * 32;
        nimg[i] = p / 3136;
        int rem = p - nimg[i] * 3136;
        hh[i] = rem / 56;
        ww[i] = rem - hh[i] * 56;
    }

    // ---- compute-side per-lane address constants ----
    const int a_row_base = wy * 32 + (lid & 7) + ((lid >> 3) & 1) * 8;
    const int a_k_lane   = ((lid >> 4) & 1) * 16;
    const int b_row_base = wx * 32 + (lid & 7) + ((lid >> 4) & 1) * 8;
    const int b_k_lane   = ((lid >> 3) & 1) * 16;

    float acc[2][4][4];
    #pragma unroll
    for (int mt = 0; mt < 2; mt++)
        #pragma unroll
        for (int nt = 0; nt < 4; nt++)
            #pragma unroll
            for (int j = 0; j < 4; j++) acc[mt][nt][j] = 0.f;

    auto load_step = [&](int s, int stg) {
        const int tap = s >> 2;
        const int cb  = s & 3;                    // channel quarter: cb*64
        const int dh = tap / 3 - 1, dw = tap % 3 - 1;
        const uint32_t st = sbase + stg * STAGE_BYTES;
        // A: 64 rows x 128B
        #pragma unroll
        for (int i = 0; i < 2; i++) {
            const int r = r0 + i * 32;
            const int h2 = hh[i] + dh, w2 = ww[i] + dw;
            const bool valid = ((unsigned)h2 < 56u) && ((unsigned)w2 < 56u);
            const long gidx = valid
                ? (((long)(nimg[i] * 56 + h2) * 56 + w2) * 256 + cb * 64 + seg * 8)
                : 0;
            const uint32_t off = (uint32_t)(r * 128 + seg * 16);
            const uint32_t sw  = off ^ ((uint32_t)(r & 7) << 4);
            cp_async16(st + A_OFF + sw, g_xf + gidx, valid ? 16u : 0u);
        }
        // B: 128 rows x 128B
        #pragma unroll
        for (int i = 0; i < 4; i++) {
            const int r = r0 + i * 32;
            const long goff = (long)(ntile * 128 + r) * KTOT + tap * 256 + cb * 64 + seg * 8;
            const uint32_t off = (uint32_t)(r * 128 + seg * 16);
            const uint32_t sw  = off ^ ((uint32_t)(r & 7) << 4);
            cp_async16(st + B_OFF + sw, g_Wq + goff, 16u);
        }
        CP_COMMIT();
    };

    // ---- 3-stage pipelined main loop, one sync per step ----
    load_step(0, 0);
    load_step(1, 1);
    for (int s = 0; s < NSTEPS; s++) {
        CP_WAIT(1);                 // stage s landed (per-thread)
        __syncthreads();            // cross-thread visibility + protects stage (s+2)%3

        if (s + 2 < NSTEPS) load_step(s + 2, (s + 2) % 3);
        else                CP_COMMIT();   // keep group-count invariant

        const uint32_t st = sbase + (s % 3) * STAGE_BYTES;
        #pragma unroll
        for (int kstep = 0; kstep < 4; kstep++) {
            uint32_t bf[8];
            #pragma unroll
            for (int h = 0; h < 2; h++) {
                const int row = b_row_base + h * 16;
                const uint32_t kb = (uint32_t)(kstep * 32 + b_k_lane);
                const uint32_t addr = st + B_OFF + row * 128 + (kb ^ ((uint32_t)(row & 7) << 4));
                ldm_x4(bf + h * 4, addr);
            }
            uint32_t af[8];
            #pragma unroll
            for (int mt = 0; mt < 2; mt++) {
                const int row = a_row_base + mt * 16;
                const uint32_t kb = (uint32_t)(kstep * 32 + a_k_lane);
                const uint32_t addr = st + A_OFF + row * 128 + (kb ^ ((uint32_t)(row & 7) << 4));
                ldm_x4(af + mt * 4, addr);
            }
            #pragma unroll
            for (int mt = 0; mt < 2; mt++)
                #pragma unroll
                for (int nt = 0; nt < 4; nt++)
                    mma_fp16(acc[mt][nt], af + mt * 4, bf + nt * 2);
        }
    }

    // ---- epilogue: alpha*acc + bias -> out ----
    const float alpha = g_alpha;
    #pragma unroll
    for (int mt = 0; mt < 2; mt++) {
        const int m0 = mtile * 64 + wy * 32 + mt * 16 + (lid >> 2);
        #pragma unroll
        for (int nt = 0; nt < 4; nt++) {
            const int n = ntile * 128 + wx * 32 + nt * 8 + (lid & 3) * 2;
            const float2 b2 = *reinterpret_cast<const float2*>(bias + n);
            float2 v0, v1;
            v0.x = alpha * acc[mt][nt][0] + b2.x;
            v0.y = alpha * acc[mt][nt][1] + b2.y;
            v1.x = alpha * acc[mt][nt][2] + b2.x;
            v1.y = alpha * acc[mt][nt][3] + b2.y;
            *reinterpret_cast<float2*>(out + (long)m0 * 256 + n)       = v0;
            *reinterpret_cast<float2*>(out + (long)(m0 + 8) * 256 + n) = v1;
        }
    }
}

// ---------------- launch ----------------
extern "C" void kernel_launch(void* const* d_in, const int* in_sizes, int n_in,
                              void* d_out, int out_size) {
    const float* x = (const float*)d_in[0];
    const float* W = (const float*)d_in[1];
    const float* b = (const float*)d_in[2];
    float* out = (float*)d_out;

    static bool attr_set = false;
    if (!attr_set) {
        cudaFuncSetAttribute(k_conv, cudaFuncAttributeMaxDynamicSharedMemorySize,
                             3 * STAGE_BYTES);
        attr_set = true;
    }

    k_cvt_redabs<<<XELEMS / 1024, 256>>>(x, W);
    k_fin_t<<<1, 256>>>();
    k_red_alpha<<<256, 256>>>(W);
    k_fin_alpha<<<1, 256>>>();
    k_quant<<<(NW_ELEM + 255) / 256, 256>>>(W);

    dim3 grid(NPIX / 64, 2);
    k_conv<<<grid, 256, 3 * STAGE_BYTES>>>(b, out);
}

// round 14
// speedup vs baseline: 1.0746x; 1.0746x over previous
#include <cuda_runtime.h>
#include <cuda_fp16.h>
#include <cstdint>

// Problem constants
#define NPIX    100352      // 32*56*56 output pixels
#define CCH     256         // channels (in == out)
#define NW_ELEM 589824      // 3*3*256*256 weights
#define KTOT    2304        // 9 taps * 256 in-ch
#define XELEMS  25690112    // 32*56*56*256

// ---------------- scratch (device globals; no allocation) ----------------
__device__ __half g_xf[XELEMS];             // fp16 x
__device__ __half g_Wq[CCH * KTOT];         // ternary W, [oc][tap*256+ic], fp16
__device__ float g_part1[256];
__device__ float g_part2[256];
__device__ int   g_pcnt[256];
__device__ float g_t;
__device__ float g_alpha;

// ---------------- helpers ----------------
static __device__ __forceinline__ uint32_t smem_u32(const void* p) {
    uint32_t a;
    asm("{ .reg .u64 t; cvta.to.shared.u64 t, %1; cvt.u32.u64 %0, t; }"
        : "=r"(a) : "l"(p));
    return a;
}

static __device__ __forceinline__ void cp_async16(uint32_t dst, const void* src, uint32_t src_sz) {
    asm volatile("cp.async.cg.shared.global [%0], [%1], 16, %2;"
                 :: "r"(dst), "l"(src), "r"(src_sz));
}
#define CP_COMMIT() asm volatile("cp.async.commit_group;" ::: "memory")
#define CP_WAIT(n)  asm volatile("cp.async.wait_group %0;" :: "n"(n) : "memory")

static __device__ __forceinline__ void ldm_x4(uint32_t* r, uint32_t addr) {
    asm volatile("ldmatrix.sync.aligned.m8n8.x4.shared.b16 {%0,%1,%2,%3}, [%4];"
                 : "=r"(r[0]), "=r"(r[1]), "=r"(r[2]), "=r"(r[3]) : "r"(addr));
}

static __device__ __forceinline__ void mma_fp16(float* c, const uint32_t* a, const uint32_t* b) {
    asm volatile(
        "mma.sync.aligned.m16n8k16.row.col.f32.f16.f16.f32 "
        "{%0,%1,%2,%3}, {%4,%5,%6,%7}, {%8,%9}, {%0,%1,%2,%3};"
        : "+f"(c[0]), "+f"(c[1]), "+f"(c[2]), "+f"(c[3])
        : "r"(a[0]), "r"(a[1]), "r"(a[2]), "r"(a[3]), "r"(b[0]), "r"(b[1]));
}

// ---------------- preprocessing kernels ----------------

// Fused: x -> fp16 conversion (all blocks) + |W| block-partials (blocks 0..255)
__global__ void k_cvt_redabs(const float* __restrict__ x, const float* __restrict__ W) {
    // fp16 conversion slice
    int i = (blockIdx.x * 256 + threadIdx.x) * 4;
    float4 v = *reinterpret_cast<const float4*>(x + i);
    __half2 a = __floats2half2_rn(v.x, v.y);
    __half2 b = __floats2half2_rn(v.z, v.w);
    uint2 pv;
    pv.x = *reinterpret_cast<uint32_t*>(&a);
    pv.y = *reinterpret_cast<uint32_t*>(&b);
    *reinterpret_cast<uint2*>(&g_xf[i]) = pv;

    // |W| reduction on the first 256 blocks
    if (blockIdx.x < 256) {
        __shared__ float s[256];
        float acc = 0.f;
        for (int j = blockIdx.x * 256 + threadIdx.x; j < NW_ELEM; j += 256 * 256)
            acc += fabsf(W[j]);
        s[threadIdx.x] = acc;
        __syncthreads();
        for (int o = 128; o > 0; o >>= 1) {
            if (threadIdx.x < o) s[threadIdx.x] += s[threadIdx.x + o];
            __syncthreads();
        }
        if (threadIdx.x == 0) g_part1[blockIdx.x] = s[0];
    }
}

__global__ void k_fin_t() {
    __shared__ float s[256];
    s[threadIdx.x] = g_part1[threadIdx.x];
    __syncthreads();
    for (int o = 128; o > 0; o >>= 1) {
        if (threadIdx.x < o) s[threadIdx.x] += s[threadIdx.x + o];
        __syncthreads();
    }
    if (threadIdx.x == 0) g_t = 0.7f * s[0] / (float)NW_ELEM;
}

__global__ void k_red_alpha(const float* __restrict__ W) {
    __shared__ float s[256];
    __shared__ int   sc[256];
    float t = g_t;
    float acc = 0.f;
    int cnt = 0;
    for (int i = blockIdx.x * 256 + threadIdx.x; i < NW_ELEM; i += 256 * 256) {
        float w = W[i];
        if (w > t)       { acc += w;  cnt++; }
        else if (w < -t) { acc -= w;  cnt++; }
    }
    s[threadIdx.x] = acc; sc[threadIdx.x] = cnt;
    __syncthreads();
    for (int o = 128; o > 0; o >>= 1) {
        if (threadIdx.x < o) { s[threadIdx.x] += s[threadIdx.x + o]; sc[threadIdx.x] += sc[threadIdx.x + o]; }
        __syncthreads();
    }
    if (threadIdx.x == 0) { g_part2[blockIdx.x] = s[0]; g_pcnt[blockIdx.x] = sc[0]; }
}

__global__ void k_fin_alpha() {
    __shared__ float s[256];
    __shared__ int   sc[256];
    s[threadIdx.x] = g_part2[threadIdx.x];
    sc[threadIdx.x] = g_pcnt[threadIdx.x];
    __syncthreads();
    for (int o = 128; o > 0; o >>= 1) {
        if (threadIdx.x < o) { s[threadIdx.x] += s[threadIdx.x + o]; sc[threadIdx.x] += sc[threadIdx.x + o]; }
        __syncthreads();
    }
    if (threadIdx.x == 0) g_alpha = s[0] / (float)sc[0];
}

// ternarize W into fp16 GEMM-B layout: g_Wq[oc][tap*256+ic]
__global__ void k_quant(const float* __restrict__ W) {
    int i = blockIdx.x * 256 + threadIdx.x;       // i = (tap*256+ic)*256 + oc
    if (i >= NW_ELEM) return;
    float t = g_t;
    float w = W[i];
    float q = (w > t) ? 1.f : ((w < -t) ? -1.f : 0.f);
    int oc = i & 255;
    int rest = i >> 8;                            // tap*256 + ic
    g_Wq[oc * KTOT + rest] = __float2half_rn(q);
}

// ---------------- main implicit-GEMM conv (mma.sync, arch-generic) -----------
// CTA: 256 threads (8 warps), tile M=128 (pixels) x N=128 (out-ch half).
// Grid: (784 M-tiles, 2 N-tiles) = 1568 CTAs; 2 CTAs resident per SM.
// K loop: 36 steps of (tap 0..8, chan-block 0..3), K=64/step; stages
//   A[128x64], B[128x64] (fp16, 128B rows, XOR swizzle) in a 3-stage
//   cp.async pipeline (32KB/stage, 96KB dynamic smem).
// Warp grid 2(M) x 4(N); warp tile 64x32 -> 4x4 m16n8k16 mma, 64 accum regs.
// One __syncthreads per step: WAIT(1) -> sync -> issue load(s+2) -> compute(s).

#define STAGE_BYTES 32768
#define A_OFF 0
#define B_OFF 16384
#define NSTEPS 36

__global__ void __launch_bounds__(256, 2)
k_conv(const float* __restrict__ bias, float* __restrict__ out) {
    extern __shared__ __align__(1024) uint8_t smem[];
    const uint32_t sbase = smem_u32(smem);

    const int tid = threadIdx.x;
    const int wid = tid >> 5;
    const int lid = tid & 31;
    const int wy  = wid & 1;        // M half (0/1 -> 64 rows)
    const int wx  = wid >> 1;       // N col (0..3 -> 32 out-ch)
    const int mtile = blockIdx.x;
    const int ntile = blockIdx.y;

    // ---- loader precompute ----
    const int seg = tid & 7;        // 16B segment within 128B row
    const int r0  = tid >> 3;       // base row 0..31; rows r0 + {0,32,64,96}
    int nimg[4], hh[4], ww[4];
    #pragma unroll
    for (int i = 0; i < 4; i++) {
        int p = mtile * 128 + r0 + i * 32;
        nimg[i] = p / 3136;
        int rem = p - nimg[i] * 3136;
        hh[i] = rem / 56;
        ww[i] = rem - hh[i] * 56;
    }

    // ---- compute-side per-lane address constants ----
    const int a_row_base = wy * 64 + (lid & 7) + ((lid >> 3) & 1) * 8;
    const int a_k_lane   = ((lid >> 4) & 1) * 16;
    const int b_row_base = wx * 32 + (lid & 7) + ((lid >> 4) & 1) * 8;
    const int b_k_lane   = ((lid >> 3) & 1) * 16;

    float acc[4][4][4];
    #pragma unroll
    for (int mt = 0; mt < 4; mt++)
        #pragma unroll
        for (int nt = 0; nt < 4; nt++)
            #pragma unroll
            for (int j = 0; j < 4; j++) acc[mt][nt][j] = 0.f;

    auto load_step = [&](int s, int stg) {
        const int tap = s >> 2;
        const int cb  = s & 3;
        const int dh = tap / 3 - 1, dw = tap % 3 - 1;
        const uint32_t st = sbase + stg * STAGE_BYTES;
        #pragma unroll
        for (int i = 0; i < 4; i++) {
            const int r = r0 + i * 32;
            const int h2 = hh[i] + dh, w2 = ww[i] + dw;
            const bool valid = ((unsigned)h2 < 56u) && ((unsigned)w2 < 56u);
            const long gidx = valid
                ? (((long)(nimg[i] * 56 + h2) * 56 + w2) * 256 + cb * 64 + seg * 8)
                : 0;
            const uint32_t off = (uint32_t)(r * 128 + seg * 16);
            const uint32_t sw  = off ^ ((uint32_t)(r & 7) << 4);
            cp_async16(st + A_OFF + sw, g_xf + gidx, valid ? 16u : 0u);
        }
        #pragma unroll
        for (int i = 0; i < 4; i++) {
            const int r = r0 + i * 32;                       // B row within tile
            const long goff = (long)(ntile * 128 + r) * KTOT + tap * 256 + cb * 64 + seg * 8;
            const uint32_t off = (uint32_t)(r * 128 + seg * 16);
            const uint32_t sw  = off ^ ((uint32_t)(r & 7) << 4);
            cp_async16(st + B_OFF + sw, g_Wq + goff, 16u);
        }
        CP_COMMIT();
    };

    // ---- 3-stage pipelined main loop, one sync per step ----
    load_step(0, 0);
    load_step(1, 1);
    for (int s = 0; s < NSTEPS; s++) {
        CP_WAIT(1);                 // stage s landed (per-thread)
        __syncthreads();            // cross-thread visibility + protects stage (s+2)%3

        if (s + 2 < NSTEPS) load_step(s + 2, (s + 2) % 3);
        else                CP_COMMIT();   // keep group-count invariant

        const uint32_t st = sbase + (s % 3) * STAGE_BYTES;
        #pragma unroll
        for (int kstep = 0; kstep < 4; kstep++) {
            uint32_t bf[8];
            #pragma unroll
            for (int h = 0; h < 2; h++) {
                const int row = b_row_base + h * 16;
                const uint32_t kb = (uint32_t)(kstep * 32 + b_k_lane);
                const uint32_t addr = st + B_OFF + row * 128 + (kb ^ ((uint32_t)(row & 7) << 4));
                ldm_x4(bf + h * 4, addr);
            }
            uint32_t af[16];
            #pragma unroll
            for (int mt = 0; mt < 4; mt++) {
                const int row = a_row_base + mt * 16;
                const uint32_t kb = (uint32_t)(kstep * 32 + a_k_lane);
                const uint32_t addr = st + A_OFF + row * 128 + (kb ^ ((uint32_t)(row & 7) << 4));
                ldm_x4(af + mt * 4, addr);
            }
            #pragma unroll
            for (int mt = 0; mt < 4; mt++)
                #pragma unroll
                for (int nt = 0; nt < 4; nt++)
                    mma_fp16(acc[mt][nt], af + mt * 4, bf + nt * 2);
        }
    }

    // ---- epilogue: alpha*acc + bias -> out ----
    const float alpha = g_alpha;
    #pragma unroll
    for (int mt = 0; mt < 4; mt++) {
        const int m0 = mtile * 128 + wy * 64 + mt * 16 + (lid >> 2);
        #pragma unroll
        for (int nt = 0; nt < 4; nt++) {
            const int n = ntile * 128 + wx * 32 + nt * 8 + (lid & 3) * 2;
            const float2 b2 = *reinterpret_cast<const float2*>(bias + n);
            float2 v0, v1;
            v0.x = alpha * acc[mt][nt][0] + b2.x;
            v0.y = alpha * acc[mt][nt][1] + b2.y;
            v1.x = alpha * acc[mt][nt][2] + b2.x;
            v1.y = alpha * acc[mt][nt][3] + b2.y;
            *reinterpret_cast<float2*>(out + (long)m0 * 256 + n)       = v0;
            *reinterpret_cast<float2*>(out + (long)(m0 + 8) * 256 + n) = v1;
        }
    }
}

// ---------------- launch ----------------
extern "C" void kernel_launch(void* const* d_in, const int* in_sizes, int n_in,
                              void* d_out, int out_size) {
    const float* x = (const float*)d_in[0];
    const float* W = (const float*)d_in[1];
    const float* b = (const float*)d_in[2];
    float* out = (float*)d_out;

    static bool attr_set = false;
    if (!attr_set) {
        cudaFuncSetAttribute(k_conv, cudaFuncAttributeMaxDynamicSharedMemorySize,
                             3 * STAGE_BYTES);
        attr_set = true;
    }

    k_cvt_redabs<<<XELEMS / 1024, 256>>>(x, W);
    k_fin_t<<<1, 256>>>();
    k_red_alpha<<<256, 256>>>(W);
    k_fin_alpha<<<1, 256>>>();
    k_quant<<<(NW_ELEM + 255) / 256, 256>>>(W);

    dim3 grid(NPIX / 128, 2);
    k_conv<<<grid, 256, 3 * STAGE_BYTES>>>(b, out);
}

// round 16
// speedup vs baseline: 1.0791x; 1.0041x over previous
#include <cuda_runtime.h>
#include <cuda_fp16.h>
#include <cstdint>

// Problem constants
#define NPIX    100352      // 32*56*56 output pixels
#define CCH     256         // channels (in == out)
#define NW_ELEM 589824      // 3*3*256*256 weights
#define KTOT    2304        // 9 taps * 256 in-ch
#define XELEMS  25690112    // 32*56*56*256

// ---------------- scratch (device globals; no allocation) ----------------
__device__ __half g_xf[XELEMS];             // fp16 x
__device__ __half g_Wq[CCH * KTOT];         // ternary W, [oc][tap*256+ic], fp16
__device__ float g_part1[256];              // |W| partials
__device__ float g_part2[256];              // alpha sum partials
__device__ int   g_pcnt[256];               // alpha count partials

// ---------------- helpers ----------------
static __device__ __forceinline__ uint32_t smem_u32(const void* p) {
    uint32_t a;
    asm("{ .reg .u64 t; cvta.to.shared.u64 t, %1; cvt.u32.u64 %0, t; }"
        : "=r"(a) : "l"(p));
    return a;
}

static __device__ __forceinline__ void cp_async16(uint32_t dst, const void* src, uint32_t src_sz) {
    asm volatile("cp.async.cg.shared.global [%0], [%1], 16, %2;"
                 :: "r"(dst), "l"(src), "r"(src_sz));
}
#define CP_COMMIT() asm volatile("cp.async.commit_group;" ::: "memory")
#define CP_WAIT(n)  asm volatile("cp.async.wait_group %0;" :: "n"(n) : "memory")

static __device__ __forceinline__ void ldm_x4(uint32_t* r, uint32_t addr) {
    asm volatile("ldmatrix.sync.aligned.m8n8.x4.shared.b16 {%0,%1,%2,%3}, [%4];"
                 : "=r"(r[0]), "=r"(r[1]), "=r"(r[2]), "=r"(r[3]) : "r"(addr));
}

static __device__ __forceinline__ void mma_fp16(float* c, const uint32_t* a, const uint32_t* b) {
    asm volatile(
        "mma.sync.aligned.m16n8k16.row.col.f32.f16.f16.f32 "
        "{%0,%1,%2,%3}, {%4,%5,%6,%7}, {%8,%9}, {%0,%1,%2,%3};"
        : "+f"(c[0]), "+f"(c[1]), "+f"(c[2]), "+f"(c[3])
        : "r"(a[0]), "r"(a[1]), "r"(a[2]), "r"(a[3]), "r"(b[0]), "r"(b[1]));
}

// ---------------- preprocessing kernels ----------------

// K1: x -> fp16 conversion (all blocks) + |W| block-partials (blocks 0..255)
__global__ void k_cvt_redabs(const float* __restrict__ x, const float* __restrict__ W) {
    int i = (blockIdx.x * 256 + threadIdx.x) * 4;
    float4 v = *reinterpret_cast<const float4*>(x + i);
    __half2 a = __floats2half2_rn(v.x, v.y);
    __half2 b = __floats2half2_rn(v.z, v.w);
    uint2 pv;
    pv.x = *reinterpret_cast<uint32_t*>(&a);
    pv.y = *reinterpret_cast<uint32_t*>(&b);
    *reinterpret_cast<uint2*>(&g_xf[i]) = pv;

    if (blockIdx.x < 256) {
        __shared__ float s[256];
        float acc = 0.f;
        for (int j = blockIdx.x * 256 + threadIdx.x; j < NW_ELEM; j += 256 * 256)
            acc += fabsf(W[j]);
        s[threadIdx.x] = acc;
        __syncthreads();
        for (int o = 128; o > 0; o >>= 1) {
            if (threadIdx.x < o) s[threadIdx.x] += s[threadIdx.x + o];
            __syncthreads();
        }
        if (threadIdx.x == 0) g_part1[blockIdx.x] = s[0];
    }
}

// K2: inline t-finalize (per block, deterministic tree) + ternarize W into
//     g_Wq[oc][tap*256+ic] + alpha partials (blocks 0..255).
// Grid: 2304 blocks x 256 threads covers NW_ELEM exactly.
__global__ void k_alpha_quant(const float* __restrict__ W) {
    __shared__ float s[256];
    __shared__ int   sc[256];
    const int tid = threadIdx.x;

    // finalize t from g_part1 (identical tree order as before -> bit-identical t)
    s[tid] = g_part1[tid];
    __syncthreads();
    for (int o = 128; o > 0; o >>= 1) {
        if (tid < o) s[tid] += s[tid + o];
        __syncthreads();
    }
    const float t = 0.7f * s[0] / (float)NW_ELEM;
    __syncthreads();   // everyone has read s[0]; safe to reuse s below

    // quantize this block's W slice
    {
        const int i = blockIdx.x * 256 + tid;   // i = (tap*256+ic)*256 + oc
        const float w = W[i];
        const float q = (w > t) ? 1.f : ((w < -t) ? -1.f : 0.f);
        const int oc = i & 255;
        const int rest = i >> 8;                // tap*256 + ic
        g_Wq[oc * KTOT + rest] = __float2half_rn(q);
    }

    // alpha partials on blocks 0..255 (same strided order as before)
    if (blockIdx.x < 256) {
        float acc = 0.f;
        int cnt = 0;
        for (int j = blockIdx.x * 256 + tid; j < NW_ELEM; j += 256 * 256) {
            const float w = W[j];
            if (w > t)       { acc += w;  cnt++; }
            else if (w < -t) { acc -= w;  cnt++; }
        }
        s[tid] = acc; sc[tid] = cnt;
        __syncthreads();
        for (int o = 128; o > 0; o >>= 1) {
            if (tid < o) { s[tid] += s[tid + o]; sc[tid] += sc[tid + o]; }
            __syncthreads();
        }
        if (tid == 0) { g_part2[blockIdx.x] = s[0]; g_pcnt[blockIdx.x] = sc[0]; }
    }
}

// ---------------- main implicit-GEMM conv (mma.sync, arch-generic) -----------
// CTA: 256 threads (8 warps), tile M=128 (pixels) x N=128 (out-ch half).
// Grid: (784 M-tiles, 2 N-tiles) = 1568 CTAs; 2 CTAs resident per SM.
// K loop: 36 steps of (tap 0..8, chan-block 0..3), K=64/step; stages
//   A[128x64], B[128x64] (fp16, 128B rows, XOR swizzle) in a 3-stage
//   cp.async pipeline (32KB/stage, 96KB dynamic smem).
// Warp grid 2(M) x 4(N); warp tile 64x32 -> 4x4 m16n8k16 mma, 64 accum regs.
// One __syncthreads per step: WAIT(1) -> sync -> issue load(s+2) -> compute(s).
// Epilogue finalizes alpha from g_part2/g_pcnt in-kernel (smem tree).

#define STAGE_BYTES 32768
#define A_OFF 0
#define B_OFF 16384
#define NSTEPS 36

__global__ void __launch_bounds__(256, 2)
k_conv(const float* __restrict__ bias, float* __restrict__ out) {
    extern __shared__ __align__(1024) uint8_t smem[];
    const uint32_t sbase = smem_u32(smem);

    const int tid = threadIdx.x;
    const int wid = tid >> 5;
    const int lid = tid & 31;
    const int wy  = wid & 1;        // M half (0/1 -> 64 rows)
    const int wx  = wid >> 1;       // N col (0..3 -> 32 out-ch)
    const int mtile = blockIdx.x;
    const int ntile = blockIdx.y;

    // ---- loader precompute ----
    const int seg = tid & 7;        // 16B segment within 128B row
    const int r0  = tid >> 3;       // base row 0..31; rows r0 + {0,32,64,96}
    int nimg[4], hh[4], ww[4];
    #pragma unroll
    for (int i = 0; i < 4; i++) {
        int p = mtile * 128 + r0 + i * 32;
        nimg[i] = p / 3136;
        int rem = p - nimg[i] * 3136;
        hh[i] = rem / 56;
        ww[i] = rem - hh[i] * 56;
    }

    // ---- compute-side per-lane address constants ----
    const int a_row_base = wy * 64 + (lid & 7) + ((lid >> 3) & 1) * 8;
    const int a_k_lane   = ((lid >> 4) & 1) * 16;
    const int b_row_base = wx * 32 + (lid & 7) + ((lid >> 4) & 1) * 8;
    const int b_k_lane   = ((lid >> 3) & 1) * 16;

    float acc[4][4][4];
    #pragma unroll
    for (int mt = 0; mt < 4; mt++)
        #pragma unroll
        for (int nt = 0; nt < 4; nt++)
            #pragma unroll
            for (int j = 0; j < 4; j++) acc[mt][nt][j] = 0.f;

    auto load_step = [&](int s, int stg) {
        const int tap = s >> 2;
        const int cb  = s & 3;
        const int dh = tap / 3 - 1, dw = tap % 3 - 1;
        const uint32_t st = sbase + stg * STAGE_BYTES;
        #pragma unroll
        for (int i = 0; i < 4; i++) {
            const int r = r0 + i * 32;
            const int h2 = hh[i] + dh, w2 = ww[i] + dw;
            const bool valid = ((unsigned)h2 < 56u) && ((unsigned)w2 < 56u);
            const long gidx = valid
                ? (((long)(nimg[i] * 56 + h2) * 56 + w2) * 256 + cb * 64 + seg * 8)
                : 0;
            const uint32_t off = (uint32_t)(r * 128 + seg * 16);
            const uint32_t sw  = off ^ ((uint32_t)(r & 7) << 4);
            cp_async16(st + A_OFF + sw, g_xf + gidx, valid ? 16u : 0u);
        }
        #pragma unroll
        for (int i = 0; i < 4; i++) {
            const int r = r0 + i * 32;                       // B row within tile
            const long goff = (long)(ntile * 128 + r) * KTOT + tap * 256 + cb * 64 + seg * 8;
            const uint32_t off = (uint32_t)(r * 128 + seg * 16);
            const uint32_t sw  = off ^ ((uint32_t)(r & 7) << 4);
            cp_async16(st + B_OFF + sw, g_Wq + goff, 16u);
        }
        CP_COMMIT();
    };

    // ---- 3-stage pipelined main loop, one sync per step ----
    load_step(0, 0);
    load_step(1, 1);
    for (int s = 0; s < NSTEPS; s++) {
        CP_WAIT(1);                 // stage s landed (per-thread)
        __syncthreads();            // cross-thread visibility + protects stage (s+2)%3

        if (s + 2 < NSTEPS) load_step(s + 2, (s + 2) % 3);
        else                CP_COMMIT();   // keep group-count invariant

        const uint32_t st = sbase + (s % 3) * STAGE_BYTES;
        #pragma unroll
        for (int kstep = 0; kstep < 4; kstep++) {
            uint32_t bf[8];
            #pragma unroll
            for (int h = 0; h < 2; h++) {
                const int row = b_row_base + h * 16;
                const uint32_t kb = (uint32_t)(kstep * 32 + b_k_lane);
                const uint32_t addr = st + B_OFF + row * 128 + (kb ^ ((uint32_t)(row & 7) << 4));
                ldm_x4(bf + h * 4, addr);
            }
            uint32_t af[16];
            #pragma unroll
            for (int mt = 0; mt < 4; mt++) {
                const int row = a_row_base + mt * 16;
                const uint32_t kb = (uint32_t)(kstep * 32 + a_k_lane);
                const uint32_t addr = st + A_OFF + row * 128 + (kb ^ ((uint32_t)(row & 7) << 4));
                ldm_x4(af + mt * 4, addr);
            }
            #pragma unroll
            for (int mt = 0; mt < 4; mt++)
                #pragma unroll
                for (int nt = 0; nt < 4; nt++)
                    mma_fp16(acc[mt][nt], af + mt * 4, bf + nt * 2);
        }
    }

    // ---- finalize alpha in-kernel (deterministic tree, reuse pipeline smem) ----
    __syncthreads();                       // all warps done reading stage smem
    float* sred = reinterpret_cast<float*>(smem);
    int*   cred = reinterpret_cast<int*>(smem + 1024);
    sred[tid] = g_part2[tid];              // tid 0..255 <-> partial 0..255
    cred[tid] = g_pcnt[tid];
    __syncthreads();
    for (int o = 128; o > 0; o >>= 1) {
        if (tid < o) { sred[tid] += sred[tid + o]; cred[tid] += cred[tid + o]; }
        __syncthreads();
    }
    const float alpha = sred[0] / (float)cred[0];

    // ---- epilogue: alpha*acc + bias -> out ----
    #pragma unroll
    for (int mt = 0; mt < 4; mt++) {
        const int m0 = mtile * 128 + wy * 64 + mt * 16 + (lid >> 2);
        #pragma unroll
        for (int nt = 0; nt < 4; nt++) {
            const int n = ntile * 128 + wx * 32 + nt * 8 + (lid & 3) * 2;
            const float2 b2 = *reinterpret_cast<const float2*>(bias + n);
            float2 v0, v1;
            v0.x = alpha * acc[mt][nt][0] + b2.x;
            v0.y = alpha * acc[mt][nt][1] + b2.y;
            v1.x = alpha * acc[mt][nt][2] + b2.x;
            v1.y = alpha * acc[mt][nt][3] + b2.y;
            *reinterpret_cast<float2*>(out + (long)m0 * 256 + n)       = v0;
            *reinterpret_cast<float2*>(out + (long)(m0 + 8) * 256 + n) = v1;
        }
    }
}

// ---------------- launch ----------------
extern "C" void kernel_launch(void* const* d_in, const int* in_sizes, int n_in,
                              void* d_out, int out_size) {
    const float* x = (const float*)d_in[0];
    const float* W = (const float*)d_in[1];
    const float* b = (const float*)d_in[2];
    float* out = (float*)d_out;

    cudaFuncSetAttribute(k_conv, cudaFuncAttributeMaxDynamicSharedMemorySize,
                         3 * STAGE_BYTES);

    k_cvt_redabs<<<XELEMS / 1024, 256>>>(x, W);
    k_alpha_quant<<<NW_ELEM / 256, 256>>>(W);

    dim3 grid(NPIX / 128, 2);
    k_conv<<<grid, 256, 3 * STAGE_BYTES>>>(b, out);
}